// round 2
// baseline (speedup 1.0000x reference)
#include <cuda_runtime.h>
#include <cstdint>

#define D1    200
#define NENT  100000
#define BATCH 1024
#define NREL  11
#define KDIM  80   // DS+DA+DO = 30+30+20

__constant__ int c_perm[NREL] = {8, 0, 3, 9, 4, 5, 6, 7, 1, 10, 2};

// Scratch (device globals: no allocations allowed)
__device__ float g_M[NREL * D1 * D1];   // 11 relation matrices, 1.76 MB
__device__ float g_x[BATCH * D1];       // gathered entities (raw)
__device__ float g_y[BATCH * D1];       // after W*x (then BN1'd in place)
__device__ float g_m0[D1], g_r0[D1], g_m1[D1], g_r1[D1];
__device__ int   g_rel[BATCH];

// ---------------------------------------------------------------------------
// K1: build M[rel][j][k] = sum_i R[rel,i] * W_i(j,k) using closed-form indices
// ---------------------------------------------------------------------------
__global__ void k_build_M(const float* __restrict__ R1, const float* __restrict__ R2,
                          const float* __restrict__ R3, const float* __restrict__ W1,
                          const float* __restrict__ W2, const float* __restrict__ W3) {
    __shared__ float Rs[NREL * KDIM];
    for (int t = threadIdx.x; t < NREL * KDIM; t += blockDim.x) {
        int rel = t / KDIM, c = t % KDIM;
        float v = 0.f;
        if (rel < 3)      { if (c < 30) v = R1[rel * 30 + c]; }
        else if (rel < 8) { if (c >= 30 && c < 60) v = R2[(rel - 3) * 30 + (c - 30)]; }
        else              { v = R3[(rel - 8) * KDIM + c]; }
        Rs[t] = v;
    }
    __syncthreads();

    int idx = blockIdx.x * blockDim.x + threadIdx.x;
    if (idx >= D1 * D1) return;
    int j = idx / D1, k = idx % D1;
    int p = min(j, k), q = max(j, k);

    float acc[NREL];
#pragma unroll
    for (int r = 0; r < NREL; r++) acc[r] = 0.f;

    // symmetric block (W1): packed upper-triangle-with-diagonal index
    int s = p * (2 * D1 - p + 1) / 2 + (q - p);
    for (int i = 0; i < 30; i++) {
        float w = W1[i * (D1 * (D1 + 1) / 2) + s];
#pragma unroll
        for (int r = 0; r < NREL; r++) acc[r] += Rs[r * KDIM + i] * w;
    }
    // antisymmetric block (W2): strict upper index, sign-flipped below diagonal
    if (j != k) {
        int u = p * (2 * D1 - p - 1) / 2 + (q - p - 1);
        float sgn = (k > j) ? 1.f : -1.f;
        for (int i = 0; i < 30; i++) {
            float w = sgn * W2[i * (D1 * (D1 - 1) / 2) + u];
#pragma unroll
            for (int r = 0; r < NREL; r++) acc[r] += Rs[r * KDIM + 30 + i] * w;
        }
    }
    // free block (W3)
    for (int i = 0; i < 20; i++) {
        float w = W3[i * D1 * D1 + idx];
#pragma unroll
        for (int r = 0; r < NREL; r++) acc[r] += Rs[r * KDIM + 60 + i] * w;
    }
#pragma unroll
    for (int r = 0; r < NREL; r++) g_M[r * D1 * D1 + idx] = acc[r];
}

// ---------------------------------------------------------------------------
// K2: gather E rows + resolve permuted relation ids
// ---------------------------------------------------------------------------
__global__ void k_gather(const float* __restrict__ E, const int* __restrict__ e1,
                         const int* __restrict__ ridx) {
    int i = blockIdx.x * blockDim.x + threadIdx.x;
    if (i < BATCH) g_rel[i] = c_perm[ridx[i]];
    for (int t = i; t < BATCH * D1; t += gridDim.x * blockDim.x) {
        int b = t / D1, d = t % D1;
        g_x[t] = E[e1[b] * D1 + d];
    }
}

// ---------------------------------------------------------------------------
// K3: per-feature batch stats (biased var, eps=1e-5). which=0 -> g_x, 1 -> g_y
// ---------------------------------------------------------------------------
__global__ void k_stats(int which) {
    const float* src = which ? g_y : g_x;
    int d = blockIdx.x;
    __shared__ float sh[16], sh2[16];
    float s = 0.f, s2 = 0.f;
    for (int b = threadIdx.x; b < BATCH; b += blockDim.x) {
        float v = src[b * D1 + d];
        s += v; s2 += v * v;
    }
#pragma unroll
    for (int o = 16; o; o >>= 1) {
        s  += __shfl_down_sync(0xFFFFFFFFu, s,  o);
        s2 += __shfl_down_sync(0xFFFFFFFFu, s2, o);
    }
    int w = threadIdx.x >> 5, l = threadIdx.x & 31;
    if (l == 0) { sh[w] = s; sh2[w] = s2; }
    __syncthreads();
    if (threadIdx.x == 0) {
        float a = 0.f, b2 = 0.f;
        int nw = blockDim.x >> 5;
        for (int i = 0; i < nw; i++) { a += sh[i]; b2 += sh2[i]; }
        float m   = a  * (1.f / BATCH);
        float var = b2 * (1.f / BATCH) - m * m;
        if (which) { g_m1[d] = m; g_r1[d] = rsqrtf(var + 1e-5f); }
        else       { g_m0[d] = m; g_r0[d] = rsqrtf(var + 1e-5f); }
    }
}

// ---------------------------------------------------------------------------
// K4: y[b,k] = sum_j M[rel_b][j][k] * BN0(x)[b,j]
// ---------------------------------------------------------------------------
__global__ void k_wx(const float* __restrict__ g0, const float* __restrict__ b0) {
    int b = blockIdx.x;
    __shared__ float xs[D1];
    for (int d = threadIdx.x; d < D1; d += blockDim.x)
        xs[d] = (g_x[b * D1 + d] - g_m0[d]) * g_r0[d] * g0[d] + b0[d];
    __syncthreads();
    int k = threadIdx.x;
    if (k < D1) {
        const float* Mp = g_M + g_rel[b] * D1 * D1 + k;
        float a0 = 0.f, a1 = 0.f, a2 = 0.f, a3 = 0.f;
#pragma unroll 4
        for (int j = 0; j < D1; j += 4) {
            a0 += Mp[(j + 0) * D1] * xs[j + 0];
            a1 += Mp[(j + 1) * D1] * xs[j + 1];
            a2 += Mp[(j + 2) * D1] * xs[j + 2];
            a3 += Mp[(j + 3) * D1] * xs[j + 3];
        }
        g_y[b * D1 + k] = (a0 + a1) + (a2 + a3);
    }
}

// ---------------------------------------------------------------------------
// K5: BN1 normalize in place
// ---------------------------------------------------------------------------
__global__ void k_norm1(const float* __restrict__ g1, const float* __restrict__ b1) {
    int t = blockIdx.x * blockDim.x + threadIdx.x;
    if (t < BATCH * D1) {
        int d = t % D1;
        g_y[t] = (g_y[t] - g_m1[d]) * g_r1[d] * g1[d] + b1[d];
    }
}

// ---------------------------------------------------------------------------
// K6: scores = sigmoid(y @ E^T) — tf32 mma.sync GEMM
//   A = g_y (1024 x 200, row-major), B = E (100000 x 200 row-major == k x n
//   col-major for mma), C = out (1024 x 100000)
// ---------------------------------------------------------------------------
#define BM  64
#define BN  128
#define KC  40
#define LDT 44   // smem leading dim (conflict-free for frag pattern)

__device__ __forceinline__ float tf32r(float x) {
    uint32_t u;
    asm("cvt.rna.tf32.f32 %0, %1;" : "=r"(u) : "f"(x));
    return __uint_as_float(u);
}

__device__ __forceinline__ void mma8(float* d, const uint32_t* a, const uint32_t* b) {
    asm volatile(
        "mma.sync.aligned.m16n8k8.row.col.f32.tf32.tf32.f32 "
        "{%0,%1,%2,%3}, {%4,%5,%6,%7}, {%8,%9}, {%0,%1,%2,%3};\n"
        : "+f"(d[0]), "+f"(d[1]), "+f"(d[2]), "+f"(d[3])
        : "r"(a[0]), "r"(a[1]), "r"(a[2]), "r"(a[3]), "r"(b[0]), "r"(b[1]));
}

__device__ __forceinline__ float sigf(float x) {
    return __fdividef(1.f, 1.f + __expf(-x));
}

__global__ __launch_bounds__(128) void k_gemm(const float* __restrict__ E,
                                              float* __restrict__ out) {
    __shared__ float As[BM * LDT];
    __shared__ float Bs[BN * LDT];

    // x (fast axis) = M blocks so the 16 blocks sharing an E tile run together
    int bm0 = blockIdx.x * BM;
    int bn0 = blockIdx.y * BN;
    int tid = threadIdx.x;
    int warp = tid >> 5, lane = tid & 31;
    int wm = warp >> 1, wn = warp & 1;     // 2x2 warps, each computing 32x64
    int g = lane >> 2, tg = lane & 3;

    float acc[2][8][4];
#pragma unroll
    for (int im = 0; im < 2; im++)
#pragma unroll
        for (int in_ = 0; in_ < 8; in_++)
#pragma unroll
            for (int c = 0; c < 4; c++) acc[im][in_][c] = 0.f;

    for (int k0 = 0; k0 < D1; k0 += KC) {
        // A tile: 64 x 40, tf32-rounded
        for (int t = tid; t < BM * (KC / 4); t += 128) {
            int row = t / (KC / 4), c4 = (t % (KC / 4)) * 4;
            float4 v = *(const float4*)&g_y[(bm0 + row) * D1 + k0 + c4];
            v.x = tf32r(v.x); v.y = tf32r(v.y); v.z = tf32r(v.z); v.w = tf32r(v.w);
            *(float4*)&As[row * LDT + c4] = v;
        }
        // B tile: 128 x 40, guarded, tf32-rounded
        for (int t = tid; t < BN * (KC / 4); t += 128) {
            int row = t / (KC / 4), c4 = (t % (KC / 4)) * 4;
            int n = bn0 + row;
            float4 v = make_float4(0.f, 0.f, 0.f, 0.f);
            if (n < NENT) v = *(const float4*)&E[n * D1 + k0 + c4];
            v.x = tf32r(v.x); v.y = tf32r(v.y); v.z = tf32r(v.z); v.w = tf32r(v.w);
            *(float4*)&Bs[row * LDT + c4] = v;
        }
        __syncthreads();

#pragma unroll
        for (int kk = 0; kk < KC; kk += 8) {
            uint32_t a[2][4], bf[8][2];
#pragma unroll
            for (int im = 0; im < 2; im++) {
                int r = wm * 32 + im * 16 + g;
                a[im][0] = __float_as_uint(As[(r)     * LDT + kk + tg]);
                a[im][1] = __float_as_uint(As[(r + 8) * LDT + kk + tg]);
                a[im][2] = __float_as_uint(As[(r)     * LDT + kk + tg + 4]);
                a[im][3] = __float_as_uint(As[(r + 8) * LDT + kk + tg + 4]);
            }
#pragma unroll
            for (int in_ = 0; in_ < 8; in_++) {
                int c = wn * 64 + in_ * 8 + g;
                bf[in_][0] = __float_as_uint(Bs[c * LDT + kk + tg]);
                bf[in_][1] = __float_as_uint(Bs[c * LDT + kk + tg + 4]);
            }
#pragma unroll
            for (int im = 0; im < 2; im++)
#pragma unroll
                for (int in_ = 0; in_ < 8; in_++)
                    mma8(acc[im][in_], a[im], bf[in_]);
        }
        __syncthreads();
    }

    // epilogue: sigmoid + store (float2: cols tg*2, tg*2+1 are adjacent)
#pragma unroll
    for (int im = 0; im < 2; im++) {
        int row0 = bm0 + wm * 32 + im * 16 + g;
#pragma unroll
        for (int in_ = 0; in_ < 8; in_++) {
            int col = bn0 + wn * 64 + in_ * 8 + tg * 2;
            if (col < NENT) {
                float2 v0 = make_float2(sigf(acc[im][in_][0]), sigf(acc[im][in_][1]));
                float2 v1 = make_float2(sigf(acc[im][in_][2]), sigf(acc[im][in_][3]));
                *(float2*)&out[row0 * NENT + col]       = v0;
                *(float2*)&out[(row0 + 8) * NENT + col] = v1;
            }
        }
    }
}

// ---------------------------------------------------------------------------
extern "C" void kernel_launch(void* const* d_in, const int* in_sizes, int n_in,
                              void* d_out, int out_size) {
    const float* E    = (const float*)d_in[0];
    const float* R1   = (const float*)d_in[1];
    const float* R2   = (const float*)d_in[2];
    const float* R3   = (const float*)d_in[3];
    const float* W1   = (const float*)d_in[4];
    const float* W2   = (const float*)d_in[5];
    const float* W3   = (const float*)d_in[6];
    const float* g0   = (const float*)d_in[7];
    const float* b0   = (const float*)d_in[8];
    const float* g1   = (const float*)d_in[9];
    const float* b1   = (const float*)d_in[10];
    const int*   e1   = (const int*)d_in[11];
    const int*   ridx = (const int*)d_in[12];
    float* out = (float*)d_out;

    k_build_M<<<(D1 * D1 + 255) / 256, 256>>>(R1, R2, R3, W1, W2, W3);
    k_gather<<<(BATCH * D1) / 256, 256>>>(E, e1, ridx);
    k_stats<<<D1, 256>>>(0);
    k_wx<<<BATCH, 256>>>(g0, b0);
    k_stats<<<D1, 256>>>(1);
    k_norm1<<<(BATCH * D1 + 255) / 256, 256>>>(g1, b1);

    dim3 grid(BATCH / BM, (NENT + BN - 1) / BN);  // (16, 782): bm fast
    k_gemm<<<grid, 128>>>(E, out);
}